// round 1
// baseline (speedup 1.0000x reference)
#include <cuda_runtime.h>
#include <cuda_bf16.h>
#include <math.h>

// Problem constants
#define Bsz   4096
#define OBS   512
#define Tn    10
#define En    8
#define Wn    1024
#define Hn    12
#define XLD   (OBS + Tn)   // 522
#define EPSV  1e-8f

// Scratch (allocation-free: __device__ globals)
__device__ float g_obs [Bsz * OBS];            // 8 MB
__device__ float g_buf0[Bsz * En * Wn];        // 128 MB
__device__ float g_buf1[Bsz * En * Wn];        // 128 MB

// ---------------------------------------------------------------------------
// obs extraction: x[:, :512] -> contiguous (B, 512)
// ---------------------------------------------------------------------------
__global__ void extract_obs_kernel(const float* __restrict__ x, float* __restrict__ obs) {
    int b = blockIdx.x;
    const float* src = x + (size_t)b * XLD;
    float* dst = obs + (size_t)b * OBS;
    for (int k = threadIdx.x; k < OBS; k += blockDim.x)
        dst[k] = src[k];
}

// ---------------------------------------------------------------------------
// Batched-expert GEMM: C[b, e-block + n] = act( A[b] @ We + be )
//   A: (M, lda) fp32 row-major; per-expert column offset a_eoff within a row
//   W: expert e at W + e*K*1024, shape (K, 1024) row-major
//   Tile 128x128x16, 256 threads, 8x8 per thread, prefetch-to-regs pipelining
// ---------------------------------------------------------------------------
__global__ __launch_bounds__(256)
void gemm_bias_act_kernel(const float* __restrict__ A, const float* __restrict__ W,
                          const float* __restrict__ bias, float* __restrict__ C,
                          int K, int lda, int a_eoff, int ldc, int c_eoff, int relu)
{
    const int BK = 16;
    __shared__ float As[16][132];   // padded (+4) to soften transpose-store conflicts
    __shared__ float Bs[16][128];

    const int e = blockIdx.z;
    const float* Ae = A + (size_t)e * a_eoff;
    const float* We = W + (size_t)e * K * 1024;
    const float* be = bias + e * 1024;
    float*       Ce = C + (size_t)e * c_eoff;

    const int tid  = threadIdx.x;
    const int row0 = blockIdx.y * 128;
    const int col0 = blockIdx.x * 128;

    // A tile load mapping: 128 rows x 16 cols; thread loads rows (tid>>2) and (tid>>2)+64
    const int ar0 = tid >> 2;
    const int ac0 = (tid & 3) << 2;
    // B tile load mapping: 16 rows x 128 cols; thread loads rows (tid>>5) and +8
    const int bkr = tid >> 5;
    const int bc  = (tid & 31) << 2;

    const float* Aptr = Ae + (size_t)row0 * lda;
    const float* Bcol = We + col0;

    // prefetch first K-tile
    float4 a0 = *(const float4*)(Aptr + (size_t)ar0       * lda + ac0);
    float4 a1 = *(const float4*)(Aptr + (size_t)(ar0 + 64) * lda + ac0);
    float4 b0 = *(const float4*)(Bcol + (size_t)bkr       * 1024 + bc);
    float4 b1 = *(const float4*)(Bcol + (size_t)(bkr + 8) * 1024 + bc);

    float acc[8][8];
#pragma unroll
    for (int i = 0; i < 8; i++)
#pragma unroll
        for (int j = 0; j < 8; j++) acc[i][j] = 0.0f;

    const int ty = tid >> 4, tx = tid & 15;
    const int mrow = ty * 8, ncol = tx * 8;

    for (int k0 = 0; k0 < K; k0 += BK) {
        // commit staged tile to smem (A transposed)
        As[ac0 + 0][ar0] = a0.x; As[ac0 + 1][ar0] = a0.y;
        As[ac0 + 2][ar0] = a0.z; As[ac0 + 3][ar0] = a0.w;
        As[ac0 + 0][ar0 + 64] = a1.x; As[ac0 + 1][ar0 + 64] = a1.y;
        As[ac0 + 2][ar0 + 64] = a1.z; As[ac0 + 3][ar0 + 64] = a1.w;
        *(float4*)&Bs[bkr][bc]     = b0;
        *(float4*)&Bs[bkr + 8][bc] = b1;
        __syncthreads();

        const int kn = k0 + BK;
        if (kn < K) {   // prefetch next K-tile while computing this one
            a0 = *(const float4*)(Aptr + (size_t)ar0        * lda + kn + ac0);
            a1 = *(const float4*)(Aptr + (size_t)(ar0 + 64) * lda + kn + ac0);
            b0 = *(const float4*)(Bcol + (size_t)(kn + bkr)     * 1024 + bc);
            b1 = *(const float4*)(Bcol + (size_t)(kn + bkr + 8) * 1024 + bc);
        }

#pragma unroll
        for (int k = 0; k < BK; k++) {
            float4 ra0 = *(const float4*)&As[k][mrow];
            float4 ra1 = *(const float4*)&As[k][mrow + 4];
            float4 rb0 = *(const float4*)&Bs[k][ncol];
            float4 rb1 = *(const float4*)&Bs[k][ncol + 4];
            float ra[8] = {ra0.x, ra0.y, ra0.z, ra0.w, ra1.x, ra1.y, ra1.z, ra1.w};
            float rb[8] = {rb0.x, rb0.y, rb0.z, rb0.w, rb1.x, rb1.y, rb1.z, rb1.w};
#pragma unroll
            for (int i = 0; i < 8; i++)
#pragma unroll
                for (int j = 0; j < 8; j++)
                    acc[i][j] = fmaf(ra[i], rb[j], acc[i][j]);
        }
        __syncthreads();
    }

    // epilogue: bias (+relu), float4 stores
#pragma unroll
    for (int i = 0; i < 8; i++) {
        const int m = row0 + mrow + i;
#pragma unroll
        for (int j = 0; j < 8; j += 4) {
            const int n = col0 + ncol + j;
            float4 bb = *(const float4*)(be + n);
            float4 v;
            v.x = acc[i][j + 0] + bb.x;
            v.y = acc[i][j + 1] + bb.y;
            v.z = acc[i][j + 2] + bb.z;
            v.w = acc[i][j + 3] + bb.w;
            if (relu) {
                v.x = fmaxf(v.x, 0.f); v.y = fmaxf(v.y, 0.f);
                v.z = fmaxf(v.z, 0.f); v.w = fmaxf(v.w, 0.f);
            }
            *(float4*)(Ce + (size_t)m * ldc + n) = v;
        }
    }
}

// ---------------------------------------------------------------------------
// Fused Gram-Schmidt + tanh-combine + per-task head. One CTA per batch row.
// ---------------------------------------------------------------------------
__device__ __forceinline__ float block_reduce_sum(float v, float* red) {
#pragma unroll
    for (int o = 16; o > 0; o >>= 1) v += __shfl_xor_sync(0xFFFFFFFFu, v, o);
    const int lane = threadIdx.x & 31, w = threadIdx.x >> 5;
    if (lane == 0) red[w] = v;
    __syncthreads();
    float s = (threadIdx.x < 8) ? red[threadIdx.x] : 0.0f;
    if (w == 0) {
#pragma unroll
        for (int o = 4; o > 0; o >>= 1) s += __shfl_xor_sync(0xFFu, s, o);
        if (lane == 0) red[0] = s;
    }
    __syncthreads();
    s = red[0];
    __syncthreads();   // safe reuse of red on next call
    return s;
}

__global__ __launch_bounds__(256)
void gs_head_kernel(const float* __restrict__ x, const float* __restrict__ eo,
                    const float* __restrict__ te_W, const float* __restrict__ head_W,
                    const float* __restrict__ head_b, float* __restrict__ out)
{
    __shared__ float sv[En][Wn];    // 32 KB
    __shared__ float red[32];
    __shared__ float s_te[En];
    __shared__ int   s_idx;

    const int b = blockIdx.x;
    const int tid = threadIdx.x;

    // load eo row (8 x 1024 contiguous)
    {
        const float4* src = (const float4*)(eo + (size_t)b * (En * Wn));
        float4* dst = (float4*)&sv[0][0];
        for (int i = tid; i < En * Wn / 4; i += 256) dst[i] = src[i];
    }
    // te[e] = onehot @ te_W ; idx = argmax(onehot)
    if (tid < En) {
        float s = 0.0f;
        for (int t = 0; t < Tn; t++)
            s += x[(size_t)b * XLD + OBS + t] * te_W[t * En + tid];
        s_te[tid] = s;
    }
    if (tid == 0) {
        float best = -1e30f; int bi = 0;
        for (int t = 0; t < Tn; t++) {
            float v = x[(size_t)b * XLD + OBS + t];
            if (v > best) { best = v; bi = t; }
        }
        s_idx = bi;
    }
    __syncthreads();

    // ---- classical Gram-Schmidt (matches reference exactly) ----
    {
        float p = 0.0f;
        for (int k = tid; k < Wn; k += 256) { float v = sv[0][k]; p += v * v; }
        float inv = 1.0f / (sqrtf(block_reduce_sum(p, red)) + EPSV);
        for (int k = tid; k < Wn; k += 256) sv[0][k] *= inv;
        __syncthreads();
    }
    for (int i = 1; i < En; i++) {
        float part[En - 1];
#pragma unroll
        for (int j = 0; j < En - 1; j++) part[j] = 0.0f;
        for (int k = tid; k < Wn; k += 256) {
            const float v = sv[i][k];
            for (int j = 0; j < i; j++) part[j] += v * sv[j][k];
        }
        float coeff[En - 1];
        for (int j = 0; j < i; j++) coeff[j] = block_reduce_sum(part[j], red);

        float nn = 0.0f;
        for (int k = tid; k < Wn; k += 256) {
            float w = sv[i][k];
            for (int j = 0; j < i; j++) w -= coeff[j] * sv[j][k];
            sv[i][k] = w;
            nn += w * w;
        }
        float inv = 1.0f / (sqrtf(block_reduce_sum(nn, red)) + EPSV);
        for (int k = tid; k < Wn; k += 256) sv[i][k] *= inv;
        __syncthreads();
    }

    // ---- feat = tanh(sum_e basis[e]*te[e]) ; head GEMV for task idx ----
    const float* hw = head_W + (size_t)s_idx * Wn * Hn;
    float hacc[Hn];
#pragma unroll
    for (int h = 0; h < Hn; h++) hacc[h] = 0.0f;

    for (int k = tid; k < Wn; k += 256) {
        float f = 0.0f;
#pragma unroll
        for (int e = 0; e < En; e++) f += sv[e][k] * s_te[e];
        f = tanhf(f);
        const float* hwk = hw + (size_t)k * Hn;
#pragma unroll
        for (int h = 0; h < Hn; h++) hacc[h] += f * hwk[h];
    }
    for (int h = 0; h < Hn; h++) {
        float s = block_reduce_sum(hacc[h], red);
        if (tid == 0) out[(size_t)b * Hn + h] = s + head_b[s_idx * Hn + h];
    }
}

// ---------------------------------------------------------------------------
extern "C" void kernel_launch(void* const* d_in, const int* in_sizes, int n_in,
                              void* d_out, int out_size)
{
    const float* x      = (const float*)d_in[0];
    const float* te_W   = (const float*)d_in[1];
    const float* W0     = (const float*)d_in[2];
    const float* b0     = (const float*)d_in[3];
    const float* W1     = (const float*)d_in[4];
    const float* b1     = (const float*)d_in[5];
    const float* W2     = (const float*)d_in[6];
    const float* b2     = (const float*)d_in[7];
    const float* head_W = (const float*)d_in[8];
    const float* head_b = (const float*)d_in[9];
    float* out = (float*)d_out;

    float *obs = nullptr, *buf0 = nullptr, *buf1 = nullptr;
    cudaGetSymbolAddress((void**)&obs,  g_obs);
    cudaGetSymbolAddress((void**)&buf0, g_buf0);
    cudaGetSymbolAddress((void**)&buf1, g_buf1);

    extract_obs_kernel<<<Bsz, 256>>>(x, obs);

    dim3 grid(Wn / 128, Bsz / 128, En);   // (8, 32, 8)
    // L0: h0 = relu(obs @ W0 + b0)          K=512
    gemm_bias_act_kernel<<<grid, 256>>>(obs,  W0, b0, buf0, 512,  512,  0,    En * Wn, Wn, 1);
    // L1: h1 = relu(h0 @ W1 + b1)           K=1024
    gemm_bias_act_kernel<<<grid, 256>>>(buf0, W1, b1, buf1, 1024, En * Wn, Wn, En * Wn, Wn, 1);
    // L2: eo = h1 @ W2 + b2 (no relu)       K=1024  -> reuse buf0
    gemm_bias_act_kernel<<<grid, 256>>>(buf1, W2, b2, buf0, 1024, En * Wn, Wn, En * Wn, Wn, 0);

    gs_head_kernel<<<Bsz, 256>>>(x, buf0, te_W, head_W, head_b, out);
}

// round 3
// speedup vs baseline: 2.7953x; 2.7953x over previous
#include <cuda_runtime.h>
#include <cstdint>
#include <math.h>

// ---------------- problem constants ----------------
#define Bsz   4096
#define OBS   512
#define Tn    10
#define En    8
#define Wn    1024
#define Hn    12
#define XLD   (OBS + Tn)
#define EPSV  1e-8f

// ---------------- scratch (allocation-free) ----------------
__device__ float g_obs [Bsz * OBS];          // 8 MB
__device__ float g_buf0[Bsz * En * Wn];      // 128 MB
__device__ float g_buf1[Bsz * En * Wn];      // 128 MB

// ---------------- helpers ----------------
__device__ __forceinline__ uint32_t smem_u32(const void* p) {
    uint32_t a;
    asm("{ .reg .u64 t; cvta.to.shared.u64 t, %1; cvt.u32.u64 %0, t; }" : "=r"(a) : "l"(p));
    return a;
}
__device__ __forceinline__ void cp16(uint32_t dst, const void* src) {
    asm volatile("cp.async.cg.shared.global [%0], [%1], 16;" :: "r"(dst), "l"(src));
}
__device__ __forceinline__ void cp_commit() { asm volatile("cp.async.commit_group;"); }
template<int N> __device__ __forceinline__ void cp_wait() {
    asm volatile("cp.async.wait_group %0;" :: "n"(N));
}
__device__ __forceinline__ uint32_t f2tf(float f) {
    uint32_t r;
    asm("cvt.rna.tf32.f32 %0, %1;" : "=r"(r) : "f"(f));
    return r;
}
__device__ __forceinline__ void mma1688(float* c, const uint32_t* a, const uint32_t* b) {
    asm volatile(
        "mma.sync.aligned.m16n8k8.row.col.f32.tf32.tf32.f32 "
        "{%0,%1,%2,%3}, {%4,%5,%6,%7}, {%8,%9}, {%0,%1,%2,%3};"
        : "+f"(c[0]), "+f"(c[1]), "+f"(c[2]), "+f"(c[3])
        : "r"(a[0]), "r"(a[1]), "r"(a[2]), "r"(a[3]), "r"(b[0]), "r"(b[1]));
}

// ---------------------------------------------------------------------------
// obs extraction: x[:, :512] -> contiguous (B, 512)
// ---------------------------------------------------------------------------
__global__ void extract_obs_kernel(const float* __restrict__ x, float* __restrict__ obs) {
    int b = blockIdx.x;
    const float* src = x + (size_t)b * XLD;
    float* dst = obs + (size_t)b * OBS;
    for (int k = threadIdx.x; k < OBS; k += blockDim.x)
        dst[k] = src[k];
}

// ---------------------------------------------------------------------------
// TF32 mma.sync GEMM: C[m, e*Wn + n] = act( A[m, e-block] @ W[e] + b[e] )
//   CTA 128x128, BK=32, 8 warps each 64x32, 3-stage cp.async pipeline.
//   W is used directly in its native [K][N] layout (no transpose).
// ---------------------------------------------------------------------------
#define BM 128
#define BN 128
#define BK 32
#define NSTG 3
#define ALD (BK + 4)                 // 36 floats per A row
#define BLD (BN + 4)                 // 132 floats per B row
#define A_ELEMS (BM * ALD)           // 4608
#define B_ELEMS (BK * BLD)           // 4224
#define STAGE_FLOATS (A_ELEMS + B_ELEMS)
#define GEMM_SMEM (NSTG * STAGE_FLOATS * 4)   // 105984 bytes

__global__ __launch_bounds__(256, 2)
void gemm_mma_kernel(const float* __restrict__ A, const float* __restrict__ W,
                     const float* __restrict__ bias, float* __restrict__ C,
                     int K, int lda, int a_eoff, int ldc, int c_eoff, int relu)
{
    extern __shared__ float sm[];

    const int tid  = threadIdx.x;
    const int wid  = tid >> 5;
    const int lane = tid & 31;
    const int gid  = lane >> 2;     // groupID  (0..7)
    const int tig  = lane & 3;      // thread in group (0..3)
    const int wm   = (wid & 1) * 64;   // warp m offset
    const int wn   = (wid >> 1) * 32;  // warp n offset

    const int e    = blockIdx.z;
    const int row0 = blockIdx.y * BM;
    const int n0   = blockIdx.x * BN;

    const float* Ae = A + (size_t)e * a_eoff + (size_t)row0 * lda;
    const float* We = W + (size_t)e * K * Wn + n0;
    const float* be = bias + e * Wn + n0;
    float*       Ce = C + (size_t)e * c_eoff;

    const uint32_t smem_base = smem_u32(sm);

    // cp.async tile loaders ------------------------------------------------
    // A: 128 rows x 32 floats = 1024 float4 (4/thread)
    const int a_r  = tid >> 1;              // used with i*? -> recompute per i
    (void)a_r;
    auto load_tile = [&](int c) {
        const int st = c % NSTG;
        const uint32_t abase = smem_base + (uint32_t)(st * STAGE_FLOATS) * 4u;
        const uint32_t bbase = abase + A_ELEMS * 4u;
        const int k0 = c * BK;
#pragma unroll
        for (int i = 0; i < 4; i++) {       // A
            int idx = tid + i * 256;        // 0..1023
            int r = idx >> 3, ci = idx & 7; // row 0..127, col4 0..7
            cp16(abase + (uint32_t)(r * ALD + ci * 4) * 4u,
                 Ae + (size_t)r * lda + k0 + ci * 4);
        }
#pragma unroll
        for (int i = 0; i < 4; i++) {       // B: 32 rows x 128 floats = 1024 float4
            int idx = tid + i * 256;
            int r = idx >> 5, ci = idx & 31;
            cp16(bbase + (uint32_t)(r * BLD + ci * 4) * 4u,
                 We + (size_t)(k0 + r) * Wn + ci * 4);
        }
        cp_commit();
    };

    float acc[4][4][4];
#pragma unroll
    for (int i = 0; i < 4; i++)
#pragma unroll
        for (int j = 0; j < 4; j++)
#pragma unroll
            for (int r = 0; r < 4; r++) acc[i][j][r] = 0.0f;

    const int nCh = K / BK;

    load_tile(0);
    load_tile(1);

    for (int t = 0; t < nCh; t++) {
        if (t == nCh - 1) cp_wait<0>(); else cp_wait<1>();
        __syncthreads();

        if (t + 2 < nCh) load_tile(t + 2);

        const float* As = sm + (t % NSTG) * STAGE_FLOATS;
        const float* Bs = As + A_ELEMS;

#pragma unroll
        for (int kk = 0; kk < 4; kk++) {
            uint32_t af[4][4];
#pragma unroll
            for (int mt = 0; mt < 4; mt++) {
                const float* ap = As + (wm + mt * 16 + gid) * ALD + kk * 8 + tig;
                af[mt][0] = f2tf(ap[0]);
                af[mt][1] = f2tf(ap[8 * ALD]);
                af[mt][2] = f2tf(ap[4]);
                af[mt][3] = f2tf(ap[8 * ALD + 4]);
            }
            uint32_t bf[4][2];
#pragma unroll
            for (int nt = 0; nt < 4; nt++) {
                const float* bp = Bs + (kk * 8 + tig) * BLD + wn + nt * 8 + gid;
                bf[nt][0] = f2tf(bp[0]);
                bf[nt][1] = f2tf(bp[4 * BLD]);
            }
#pragma unroll
            for (int mt = 0; mt < 4; mt++)
#pragma unroll
                for (int nt = 0; nt < 4; nt++)
                    mma1688(acc[mt][nt], af[mt], bf[nt]);
        }
        __syncthreads();
    }

    // epilogue: bias (+relu), float2 stores --------------------------------
#pragma unroll
    for (int mt = 0; mt < 4; mt++) {
#pragma unroll
        for (int nt = 0; nt < 4; nt++) {
            const int col = wn + nt * 8 + tig * 2;
            const float bx = be[col], by = be[col + 1];
            const int r0 = row0 + wm + mt * 16 + gid;
            float2 v0, v1;
            v0.x = acc[mt][nt][0] + bx; v0.y = acc[mt][nt][1] + by;
            v1.x = acc[mt][nt][2] + bx; v1.y = acc[mt][nt][3] + by;
            if (relu) {
                v0.x = fmaxf(v0.x, 0.f); v0.y = fmaxf(v0.y, 0.f);
                v1.x = fmaxf(v1.x, 0.f); v1.y = fmaxf(v1.y, 0.f);
            }
            *(float2*)(Ce + (size_t)r0 * ldc + n0 + col)       = v0;
            *(float2*)(Ce + (size_t)(r0 + 8) * ldc + n0 + col) = v1;
        }
    }
}

// ---------------------------------------------------------------------------
// Fused Gram-Schmidt + tanh-combine + per-task head
// ---------------------------------------------------------------------------
__device__ __forceinline__ float block_reduce_sum(float v, float* red) {
#pragma unroll
    for (int o = 16; o > 0; o >>= 1) v += __shfl_xor_sync(0xFFFFFFFFu, v, o);
    const int lane = threadIdx.x & 31, w = threadIdx.x >> 5;
    if (lane == 0) red[w] = v;
    __syncthreads();
    float s = (threadIdx.x < 8) ? red[threadIdx.x] : 0.0f;
    if (w == 0) {
#pragma unroll
        for (int o = 4; o > 0; o >>= 1) s += __shfl_xor_sync(0xFFu, s, o);
        if (lane == 0) red[0] = s;
    }
    __syncthreads();
    s = red[0];
    __syncthreads();
    return s;
}

__global__ __launch_bounds__(256)
void gs_head_kernel(const float* __restrict__ x, const float* __restrict__ eo,
                    const float* __restrict__ te_W, const float* __restrict__ head_W,
                    const float* __restrict__ head_b, float* __restrict__ out)
{
    __shared__ float sv[En][Wn];
    __shared__ float red[32];
    __shared__ float s_te[En];
    __shared__ int   s_idx;

    const int b = blockIdx.x;
    const int tid = threadIdx.x;

    {
        const float4* src = (const float4*)(eo + (size_t)b * (En * Wn));
        float4* dst = (float4*)&sv[0][0];
        for (int i = tid; i < En * Wn / 4; i += 256) dst[i] = src[i];
    }
    if (tid < En) {
        float s = 0.0f;
        for (int t = 0; t < Tn; t++)
            s += x[(size_t)b * XLD + OBS + t] * te_W[t * En + tid];
        s_te[tid] = s;
    }
    if (tid == 0) {
        float best = -1e30f; int bi = 0;
        for (int t = 0; t < Tn; t++) {
            float v = x[(size_t)b * XLD + OBS + t];
            if (v > best) { best = v; bi = t; }
        }
        s_idx = bi;
    }
    __syncthreads();

    {
        float p = 0.0f;
        for (int k = tid; k < Wn; k += 256) { float v = sv[0][k]; p += v * v; }
        float inv = 1.0f / (sqrtf(block_reduce_sum(p, red)) + EPSV);
        for (int k = tid; k < Wn; k += 256) sv[0][k] *= inv;
        __syncthreads();
    }
    for (int i = 1; i < En; i++) {
        float part[En - 1];
#pragma unroll
        for (int j = 0; j < En - 1; j++) part[j] = 0.0f;
        for (int k = tid; k < Wn; k += 256) {
            const float v = sv[i][k];
            for (int j = 0; j < i; j++) part[j] += v * sv[j][k];
        }
        float coeff[En - 1];
        for (int j = 0; j < i; j++) coeff[j] = block_reduce_sum(part[j], red);

        float nn = 0.0f;
        for (int k = tid; k < Wn; k += 256) {
            float w = sv[i][k];
            for (int j = 0; j < i; j++) w -= coeff[j] * sv[j][k];
            sv[i][k] = w;
            nn += w * w;
        }
        float inv = 1.0f / (sqrtf(block_reduce_sum(nn, red)) + EPSV);
        for (int k = tid; k < Wn; k += 256) sv[i][k] *= inv;
        __syncthreads();
    }

    const float* hw = head_W + (size_t)s_idx * Wn * Hn;
    float hacc[Hn];
#pragma unroll
    for (int h = 0; h < Hn; h++) hacc[h] = 0.0f;

    for (int k = tid; k < Wn; k += 256) {
        float f = 0.0f;
#pragma unroll
        for (int e = 0; e < En; e++) f += sv[e][k] * s_te[e];
        f = tanhf(f);
        const float* hwk = hw + (size_t)k * Hn;
#pragma unroll
        for (int h = 0; h < Hn; h++) hacc[h] += f * hwk[h];
    }
    for (int h = 0; h < Hn; h++) {
        float s = block_reduce_sum(hacc[h], red);
        if (tid == 0) out[(size_t)b * Hn + h] = s + head_b[s_idx * Hn + h];
    }
}

// ---------------------------------------------------------------------------
extern "C" void kernel_launch(void* const* d_in, const int* in_sizes, int n_in,
                              void* d_out, int out_size)
{
    const float* x      = (const float*)d_in[0];
    const float* te_W   = (const float*)d_in[1];
    const float* W0     = (const float*)d_in[2];
    const float* b0     = (const float*)d_in[3];
    const float* W1     = (const float*)d_in[4];
    const float* b1     = (const float*)d_in[5];
    const float* W2     = (const float*)d_in[6];
    const float* b2     = (const float*)d_in[7];
    const float* head_W = (const float*)d_in[8];
    const float* head_b = (const float*)d_in[9];
    float* out = (float*)d_out;

    float *obs, *buf0, *buf1;
    cudaGetSymbolAddress((void**)&obs,  g_obs);
    cudaGetSymbolAddress((void**)&buf0, g_buf0);
    cudaGetSymbolAddress((void**)&buf1, g_buf1);

    cudaFuncSetAttribute(gemm_mma_kernel, cudaFuncAttributeMaxDynamicSharedMemorySize, GEMM_SMEM);

    extract_obs_kernel<<<Bsz, 256>>>(x, obs);

    dim3 grid(Wn / BN, Bsz / BM, En);   // (8, 32, 8)
    // L0: h0 = relu(obs @ W0 + b0), K=512
    gemm_mma_kernel<<<grid, 256, GEMM_SMEM>>>(obs,  W0, b0, buf0, 512,  512,     0,  En * Wn, Wn, 1);
    // L1: h1 = relu(h0 @ W1 + b1), K=1024
    gemm_mma_kernel<<<grid, 256, GEMM_SMEM>>>(buf0, W1, b1, buf1, 1024, En * Wn, Wn, En * Wn, Wn, 1);
    // L2: eo = h1 @ W2 + b2, K=1024
    gemm_mma_kernel<<<grid, 256, GEMM_SMEM>>>(buf1, W2, b2, buf0, 1024, En * Wn, Wn, En * Wn, Wn, 0);

    gs_head_kernel<<<Bsz, 256>>>(x, buf0, te_W, head_W, head_b, out);
}

// round 4
// speedup vs baseline: 5.4390x; 1.9458x over previous
#include <cuda_runtime.h>
#include <cuda_fp16.h>
#include <cstdint>
#include <math.h>

// ---------------- problem constants ----------------
#define Bsz   4096
#define OBS   512
#define Tn    10
#define En    8
#define Wn    1024
#define Hn    12
#define XLD   (OBS + Tn)
#define EPSV  1e-8f

// ---------------- scratch (allocation-free) ----------------
__device__ __half g_obsh[Bsz * OBS];            // 4 MB
__device__ __half g_wh  [20971520];             // 40 MB: W0h | W1h | W2h
__device__ __half g_h0  [Bsz * En * Wn];        // 64 MB
__device__ __half g_h1  [Bsz * En * Wn];        // 64 MB
__device__ float  g_eo  [Bsz * En * Wn];        // 128 MB
#define W0H_OFF 0
#define W1H_OFF (En * OBS * Wn)                 // 4194304
#define W2H_OFF (W1H_OFF + En * Wn * Wn)        // 12582912

// ---------------- helpers ----------------
__device__ __forceinline__ uint32_t smem_u32(const void* p) {
    uint32_t a;
    asm("{ .reg .u64 t; cvta.to.shared.u64 t, %1; cvt.u32.u64 %0, t; }" : "=r"(a) : "l"(p));
    return a;
}
__device__ __forceinline__ void cp16(uint32_t dst, const void* src) {
    asm volatile("cp.async.cg.shared.global [%0], [%1], 16;" :: "r"(dst), "l"(src));
}
__device__ __forceinline__ void cp_commit() { asm volatile("cp.async.commit_group;"); }
template<int N> __device__ __forceinline__ void cp_wait() {
    asm volatile("cp.async.wait_group %0;" :: "n"(N));
}
__device__ __forceinline__ void ldsm_x4(uint32_t* r, uint32_t addr) {
    asm volatile("ldmatrix.sync.aligned.m8n8.x4.shared.b16 {%0,%1,%2,%3}, [%4];"
                 : "=r"(r[0]), "=r"(r[1]), "=r"(r[2]), "=r"(r[3]) : "r"(addr));
}
__device__ __forceinline__ void ldsm_x4_trans(uint32_t* r, uint32_t addr) {
    asm volatile("ldmatrix.sync.aligned.m8n8.x4.trans.shared.b16 {%0,%1,%2,%3}, [%4];"
                 : "=r"(r[0]), "=r"(r[1]), "=r"(r[2]), "=r"(r[3]) : "r"(addr));
}
__device__ __forceinline__ void mma16816(float* c, const uint32_t* a, const uint32_t* b) {
    asm volatile(
        "mma.sync.aligned.m16n8k16.row.col.f32.f16.f16.f32 "
        "{%0,%1,%2,%3}, {%4,%5,%6,%7}, {%8,%9}, {%0,%1,%2,%3};"
        : "+f"(c[0]), "+f"(c[1]), "+f"(c[2]), "+f"(c[3])
        : "r"(a[0]), "r"(a[1]), "r"(a[2]), "r"(a[3]), "r"(b[0]), "r"(b[1]));
}

// ---------------------------------------------------------------------------
// fp32 -> fp16 weight conversion (grid-stride)
// ---------------------------------------------------------------------------
__global__ void cvt_half_kernel(const float* __restrict__ src, __half* __restrict__ dst, int n) {
    int i = (blockIdx.x * blockDim.x + threadIdx.x) * 2;
    const int stride = gridDim.x * blockDim.x * 2;
    for (; i < n; i += stride) {
        float2 v = *(const float2*)(src + i);
        *(__half2*)(dst + i) = __floats2half2_rn(v.x, v.y);
    }
}

// ---------------------------------------------------------------------------
// obs extraction + fp16 convert: x[:, :512] -> half (B, 512)
// ---------------------------------------------------------------------------
__global__ void extract_obs_kernel(const float* __restrict__ x, __half* __restrict__ obs) {
    int b = blockIdx.x;
    const float* src = x + (size_t)b * XLD;
    __half* dst = obs + (size_t)b * OBS;
    int k = threadIdx.x * 2;                      // 256 threads x 2 = 512
    *(__half2*)(dst + k) = __floats2half2_rn(src[k], src[k + 1]);
}

// ---------------------------------------------------------------------------
// FP16 mma.sync GEMM: C[m, e*Wn+n] = act( A[m, e-block] @ W[e] + b[e] )
//   CTA 128x128, BK=32, 8 warps (2x4) each 64x32, 4-stage cp.async pipeline.
//   A: half [M][lda] row-major (+ per-expert col offset). W: half [K][Wn].
//   Fragments via ldmatrix (A normal, B trans). Output half (rounded) or float.
// ---------------------------------------------------------------------------
#define BM 128
#define BN 128
#define BK 32
#define NSTG 4
#define A_RB 80                      // A row stride bytes (64 data + 16 pad)
#define B_RB 272                     // B row stride bytes (256 data + 16 pad)
#define A_BYTES (BM * A_RB)          // 10240
#define B_BYTES (BK * B_RB)          // 8704
#define STAGE_BYTES (A_BYTES + B_BYTES)
#define GEMM_SMEM (NSTG * STAGE_BYTES)   // 75776

__global__ __launch_bounds__(256, 2)
void gemm_fp16_kernel(const __half* __restrict__ A, const __half* __restrict__ W,
                      const float* __restrict__ bias, void* __restrict__ C,
                      int K, int lda, int a_eoff, int outHalf, int relu)
{
    extern __shared__ char sm[];

    const int tid  = threadIdx.x;
    const int wid  = tid >> 5;
    const int lane = tid & 31;
    const int gid  = lane >> 2;
    const int tig  = lane & 3;
    const int wm   = (wid & 1) * 64;
    const int wn   = (wid >> 1) * 32;

    const int e    = blockIdx.z;
    const int row0 = blockIdx.y * BM;
    const int n0   = blockIdx.x * BN;

    const __half* Ae = A + (size_t)e * a_eoff + (size_t)row0 * lda;
    const __half* We = W + (size_t)e * K * Wn + n0;
    const float*  be = bias + e * Wn + n0;

    const uint32_t smem_base = smem_u32(sm);

    auto load_chunk = [&](int c) {
        const int st = c % NSTG;
        const uint32_t abase = smem_base + st * STAGE_BYTES;
        const uint32_t bbase = abase + A_BYTES;
        const int k0 = c * BK;
#pragma unroll
        for (int i = 0; i < 2; i++) {            // A: 128 rows x 64B = 512 cp16
            int idx = tid + i * 256;
            int r = idx >> 2, ci = idx & 3;
            cp16(abase + (uint32_t)(r * A_RB + ci * 16),
                 Ae + (size_t)r * lda + k0 + ci * 8);
        }
#pragma unroll
        for (int i = 0; i < 2; i++) {            // B: 32 rows x 256B = 512 cp16
            int idx = tid + i * 256;
            int r = idx >> 4, ci = idx & 15;
            cp16(bbase + (uint32_t)(r * B_RB + ci * 16),
                 We + (size_t)(k0 + r) * Wn + ci * 8);
        }
    };

    float acc[4][4][4];
#pragma unroll
    for (int i = 0; i < 4; i++)
#pragma unroll
        for (int j = 0; j < 4; j++)
#pragma unroll
            for (int r = 0; r < 4; r++) acc[i][j][r] = 0.0f;

    const int nCh = K / BK;

    for (int c = 0; c < 3; c++) { load_chunk(c); cp_commit(); }

    // ldmatrix lane-address components (constant per thread)
    const int a_row_l = lane & 15;               // row within 16-row tile
    const int a_koff  = (lane >> 4) << 3;        // +8 cols for upper octets
    const int b_krow_l = lane & 15;
    const int b_noff   = (lane >> 4) << 3;

    for (int t = 0; t < nCh; t++) {
        cp_wait<2>();
        __syncthreads();

        if (t + 3 < nCh) load_chunk(t + 3);
        cp_commit();

        const uint32_t abase = smem_base + (t % NSTG) * STAGE_BYTES;
        const uint32_t bbase = abase + A_BYTES;

#pragma unroll
        for (int kk = 0; kk < 2; kk++) {
            uint32_t af[4][4];
#pragma unroll
            for (int mt = 0; mt < 4; mt++) {
                uint32_t addr = abase + (uint32_t)((wm + mt * 16 + a_row_l) * A_RB
                                                   + (kk * 16 + a_koff) * 2);
                ldsm_x4(af[mt], addr);
            }
            uint32_t bf[4][2];
#pragma unroll
            for (int np = 0; np < 2; np++) {
                uint32_t r[4];
                uint32_t addr = bbase + (uint32_t)((kk * 16 + b_krow_l) * B_RB
                                                   + (wn + np * 16 + b_noff) * 2);
                ldsm_x4_trans(r, addr);
                bf[np * 2][0]     = r[0]; bf[np * 2][1]     = r[1];
                bf[np * 2 + 1][0] = r[2]; bf[np * 2 + 1][1] = r[3];
            }
#pragma unroll
            for (int mt = 0; mt < 4; mt++)
#pragma unroll
                for (int nt = 0; nt < 4; nt++)
                    mma16816(acc[mt][nt], af[mt], bf[nt]);
        }
        __syncthreads();
    }

    // ---- epilogue ----
    if (outHalf) {
        __half* Ce = (__half*)C + (size_t)e * Wn;
#pragma unroll
        for (int mt = 0; mt < 4; mt++) {
#pragma unroll
            for (int nt = 0; nt < 4; nt++) {
                const int col = wn + nt * 8 + tig * 2;
                const float bx = be[col], by = be[col + 1];
                const int r0 = row0 + wm + mt * 16 + gid;
                float v0 = acc[mt][nt][0] + bx, v1 = acc[mt][nt][1] + by;
                float v2 = acc[mt][nt][2] + bx, v3 = acc[mt][nt][3] + by;
                if (relu) {
                    v0 = fmaxf(v0, 0.f); v1 = fmaxf(v1, 0.f);
                    v2 = fmaxf(v2, 0.f); v3 = fmaxf(v3, 0.f);
                }
                *(__half2*)(Ce + (size_t)r0 * (En * Wn) + n0 + col)       = __floats2half2_rn(v0, v1);
                *(__half2*)(Ce + (size_t)(r0 + 8) * (En * Wn) + n0 + col) = __floats2half2_rn(v2, v3);
            }
        }
    } else {
        float* Ce = (float*)C + (size_t)e * Wn;
#pragma unroll
        for (int mt = 0; mt < 4; mt++) {
#pragma unroll
            for (int nt = 0; nt < 4; nt++) {
                const int col = wn + nt * 8 + tig * 2;
                const float bx = be[col], by = be[col + 1];
                const int r0 = row0 + wm + mt * 16 + gid;
                float2 v0, v1;
                v0.x = acc[mt][nt][0] + bx; v0.y = acc[mt][nt][1] + by;
                v1.x = acc[mt][nt][2] + bx; v1.y = acc[mt][nt][3] + by;
                *(float2*)(Ce + (size_t)r0 * (En * Wn) + n0 + col)       = v0;
                *(float2*)(Ce + (size_t)(r0 + 8) * (En * Wn) + n0 + col) = v1;
            }
        }
    }
}

// ---------------------------------------------------------------------------
// Fused Gram-Schmidt + tanh-combine + per-task head
// ---------------------------------------------------------------------------
__device__ __forceinline__ float block_reduce_sum(float v, float* red) {
#pragma unroll
    for (int o = 16; o > 0; o >>= 1) v += __shfl_xor_sync(0xFFFFFFFFu, v, o);
    const int lane = threadIdx.x & 31, w = threadIdx.x >> 5;
    if (lane == 0) red[w] = v;
    __syncthreads();
    float s = (threadIdx.x < 8) ? red[threadIdx.x] : 0.0f;
    if (w == 0) {
#pragma unroll
        for (int o = 4; o > 0; o >>= 1) s += __shfl_xor_sync(0xFFu, s, o);
        if (lane == 0) red[0] = s;
    }
    __syncthreads();
    s = red[0];
    __syncthreads();
    return s;
}

__global__ __launch_bounds__(256)
void gs_head_kernel(const float* __restrict__ x, const float* __restrict__ eo,
                    const float* __restrict__ te_W, const float* __restrict__ head_W,
                    const float* __restrict__ head_b, float* __restrict__ out)
{
    __shared__ float sv[En][Wn];
    __shared__ float red[32];
    __shared__ float s_te[En];
    __shared__ int   s_idx;

    const int b = blockIdx.x;
    const int tid = threadIdx.x;

    {
        const float4* src = (const float4*)(eo + (size_t)b * (En * Wn));
        float4* dst = (float4*)&sv[0][0];
        for (int i = tid; i < En * Wn / 4; i += 256) dst[i] = src[i];
    }
    if (tid < En) {
        float s = 0.0f;
        for (int t = 0; t < Tn; t++)
            s += x[(size_t)b * XLD + OBS + t] * te_W[t * En + tid];
        s_te[tid] = s;
    }
    if (tid == 0) {
        float best = -1e30f; int bi = 0;
        for (int t = 0; t < Tn; t++) {
            float v = x[(size_t)b * XLD + OBS + t];
            if (v > best) { best = v; bi = t; }
        }
        s_idx = bi;
    }
    __syncthreads();

    {
        float p = 0.0f;
        for (int k = tid; k < Wn; k += 256) { float v = sv[0][k]; p += v * v; }
        float inv = 1.0f / (sqrtf(block_reduce_sum(p, red)) + EPSV);
        for (int k = tid; k < Wn; k += 256) sv[0][k] *= inv;
        __syncthreads();
    }
    for (int i = 1; i < En; i++) {
        float part[En - 1];
#pragma unroll
        for (int j = 0; j < En - 1; j++) part[j] = 0.0f;
        for (int k = tid; k < Wn; k += 256) {
            const float v = sv[i][k];
            for (int j = 0; j < i; j++) part[j] += v * sv[j][k];
        }
        float coeff[En - 1];
        for (int j = 0; j < i; j++) coeff[j] = block_reduce_sum(part[j], red);

        float nn = 0.0f;
        for (int k = tid; k < Wn; k += 256) {
            float w = sv[i][k];
            for (int j = 0; j < i; j++) w -= coeff[j] * sv[j][k];
            sv[i][k] = w;
            nn += w * w;
        }
        float inv = 1.0f / (sqrtf(block_reduce_sum(nn, red)) + EPSV);
        for (int k = tid; k < Wn; k += 256) sv[i][k] *= inv;
        __syncthreads();
    }

    const float* hw = head_W + (size_t)s_idx * Wn * Hn;
    float hacc[Hn];
#pragma unroll
    for (int h = 0; h < Hn; h++) hacc[h] = 0.0f;

    for (int k = tid; k < Wn; k += 256) {
        float f = 0.0f;
#pragma unroll
        for (int e = 0; e < En; e++) f += sv[e][k] * s_te[e];
        f = tanhf(f);
        const float* hwk = hw + (size_t)k * Hn;
#pragma unroll
        for (int h = 0; h < Hn; h++) hacc[h] += f * hwk[h];
    }
    for (int h = 0; h < Hn; h++) {
        float s = block_reduce_sum(hacc[h], red);
        if (tid == 0) out[(size_t)b * Hn + h] = s + head_b[s_idx * Hn + h];
    }
}

// ---------------------------------------------------------------------------
extern "C" void kernel_launch(void* const* d_in, const int* in_sizes, int n_in,
                              void* d_out, int out_size)
{
    const float* x      = (const float*)d_in[0];
    const float* te_W   = (const float*)d_in[1];
    const float* W0     = (const float*)d_in[2];
    const float* b0     = (const float*)d_in[3];
    const float* W1     = (const float*)d_in[4];
    const float* b1     = (const float*)d_in[5];
    const float* W2     = (const float*)d_in[6];
    const float* b2     = (const float*)d_in[7];
    const float* head_W = (const float*)d_in[8];
    const float* head_b = (const float*)d_in[9];
    float* out = (float*)d_out;

    __half *obsh, *wh, *h0, *h1;
    float *eo;
    cudaGetSymbolAddress((void**)&obsh, g_obsh);
    cudaGetSymbolAddress((void**)&wh,   g_wh);
    cudaGetSymbolAddress((void**)&h0,   g_h0);
    cudaGetSymbolAddress((void**)&h1,   g_h1);
    cudaGetSymbolAddress((void**)&eo,   g_eo);

    cudaFuncSetAttribute(gemm_fp16_kernel, cudaFuncAttributeMaxDynamicSharedMemorySize, GEMM_SMEM);

    // weight + input conversion
    cvt_half_kernel<<<2048, 256>>>(W0, wh + W0H_OFF, En * OBS * Wn);
    cvt_half_kernel<<<4096, 256>>>(W1, wh + W1H_OFF, En * Wn * Wn);
    cvt_half_kernel<<<4096, 256>>>(W2, wh + W2H_OFF, En * Wn * Wn);
    extract_obs_kernel<<<Bsz, 256>>>(x, obsh);

    dim3 grid(Wn / BN, Bsz / BM, En);   // (8, 32, 8)
    // L0: h0 = relu(obs @ W0 + b0), K=512, half out
    gemm_fp16_kernel<<<grid, 256, GEMM_SMEM>>>(obsh, wh + W0H_OFF, b0, h0, 512,  OBS,     0,    1, 1);
    // L1: h1 = relu(h0 @ W1 + b1), K=1024, half out
    gemm_fp16_kernel<<<grid, 256, GEMM_SMEM>>>(h0,   wh + W1H_OFF, b1, h1, 1024, En * Wn, Wn,   1, 1);
    // L2: eo = h1 @ W2 + b2, K=1024, float out
    gemm_fp16_kernel<<<grid, 256, GEMM_SMEM>>>(h1,   wh + W2H_OFF, b2, eo, 1024, En * Wn, Wn,   0, 0);

    gs_head_kernel<<<Bsz, 256>>>(x, eo, te_W, head_W, head_b, out);
}

// round 5
// speedup vs baseline: 6.0267x; 1.1081x over previous
#include <cuda_runtime.h>
#include <cuda_fp16.h>
#include <cstdint>
#include <math.h>

// ---------------- problem constants ----------------
#define Bsz   4096
#define OBS   512
#define Tn    10
#define En    8
#define Wn    1024
#define Hn    12
#define XLD   (OBS + Tn)
#define EPSV  1e-8f

// ---------------- scratch (allocation-free) ----------------
__device__ __half g_obsh[Bsz * OBS];            // 4 MB
__device__ __half g_wh  [20971520];             // 40 MB: W0h | W1h | W2h
__device__ __half g_h0  [Bsz * En * Wn];        // 64 MB
__device__ __half g_h1  [Bsz * En * Wn];        // 64 MB
__device__ float  g_eo  [Bsz * En * Wn];        // 128 MB
#define W0H_OFF 0
#define W1H_OFF (En * OBS * Wn)                 // 4194304
#define W2H_OFF (W1H_OFF + En * Wn * Wn)        // 12582912

// ---------------- helpers ----------------
__device__ __forceinline__ uint32_t smem_u32(const void* p) {
    uint32_t a;
    asm("{ .reg .u64 t; cvta.to.shared.u64 t, %1; cvt.u32.u64 %0, t; }" : "=r"(a) : "l"(p));
    return a;
}
__device__ __forceinline__ void cp16(uint32_t dst, const void* src) {
    asm volatile("cp.async.cg.shared.global [%0], [%1], 16;" :: "r"(dst), "l"(src));
}
__device__ __forceinline__ void cp_commit() { asm volatile("cp.async.commit_group;"); }
template<int N> __device__ __forceinline__ void cp_wait() {
    asm volatile("cp.async.wait_group %0;" :: "n"(N));
}
__device__ __forceinline__ void ldsm_x4(uint32_t* r, uint32_t addr) {
    asm volatile("ldmatrix.sync.aligned.m8n8.x4.shared.b16 {%0,%1,%2,%3}, [%4];"
                 : "=r"(r[0]), "=r"(r[1]), "=r"(r[2]), "=r"(r[3]) : "r"(addr));
}
__device__ __forceinline__ void ldsm_x4_trans(uint32_t* r, uint32_t addr) {
    asm volatile("ldmatrix.sync.aligned.m8n8.x4.trans.shared.b16 {%0,%1,%2,%3}, [%4];"
                 : "=r"(r[0]), "=r"(r[1]), "=r"(r[2]), "=r"(r[3]) : "r"(addr));
}
__device__ __forceinline__ void mma16816(float* c, const uint32_t* a, const uint32_t* b) {
    asm volatile(
        "mma.sync.aligned.m16n8k16.row.col.f32.f16.f16.f32 "
        "{%0,%1,%2,%3}, {%4,%5,%6,%7}, {%8,%9}, {%0,%1,%2,%3};"
        : "+f"(c[0]), "+f"(c[1]), "+f"(c[2]), "+f"(c[3])
        : "r"(a[0]), "r"(a[1]), "r"(a[2]), "r"(a[3]), "r"(b[0]), "r"(b[1]));
}

// ---------------------------------------------------------------------------
// fp32 -> fp16 weight conversion (grid-stride)
// ---------------------------------------------------------------------------
__global__ void cvt_half_kernel(const float* __restrict__ src, __half* __restrict__ dst, int n) {
    int i = (blockIdx.x * blockDim.x + threadIdx.x) * 2;
    const int stride = gridDim.x * blockDim.x * 2;
    for (; i < n; i += stride) {
        float2 v = *(const float2*)(src + i);
        *(__half2*)(dst + i) = __floats2half2_rn(v.x, v.y);
    }
}

// ---------------------------------------------------------------------------
// obs extraction + fp16 convert: x[:, :512] -> half (B, 512)
// ---------------------------------------------------------------------------
__global__ void extract_obs_kernel(const float* __restrict__ x, __half* __restrict__ obs) {
    int b = blockIdx.x;
    const float* src = x + (size_t)b * XLD;
    __half* dst = obs + (size_t)b * OBS;
    int k = threadIdx.x * 2;
    *(__half2*)(dst + k) = __floats2half2_rn(src[k], src[k + 1]);
}

// ---------------------------------------------------------------------------
// FP16 mma.sync GEMM: C[m, e*Wn+n] = act( A[m, e-block] @ W[e] + b[e] )
//   CTA 128x128, BK=32, 4 warps (2x2) each 64x64, 4-stage cp.async pipeline,
//   single __syncthreads per mainloop iteration.
// ---------------------------------------------------------------------------
#define BM 128
#define BN 128
#define BK 32
#define NSTG 4
#define A_RB 80                      // A row stride bytes (64 data + 16 pad)
#define B_RB 272                     // B row stride bytes (256 data + 16 pad)
#define A_BYTES (BM * A_RB)          // 10240
#define B_BYTES (BK * B_RB)          // 8704
#define STAGE_BYTES (A_BYTES + B_BYTES)
#define GEMM_SMEM (NSTG * STAGE_BYTES)   // 75776

__global__ __launch_bounds__(128, 2)
void gemm_fp16_kernel(const __half* __restrict__ A, const __half* __restrict__ W,
                      const float* __restrict__ bias, void* __restrict__ C,
                      int K, int lda, int a_eoff, int outHalf, int relu)
{
    extern __shared__ char sm[];

    const int tid  = threadIdx.x;
    const int wid  = tid >> 5;
    const int lane = tid & 31;
    const int gid  = lane >> 2;
    const int tig  = lane & 3;
    const int wm   = (wid & 1) * 64;    // warp m offset (0, 64)
    const int wn   = (wid >> 1) * 64;   // warp n offset (0, 64)

    const int e    = blockIdx.z;
    const int row0 = blockIdx.y * BM;
    const int n0   = blockIdx.x * BN;

    const __half* Ae = A + (size_t)e * a_eoff + (size_t)row0 * lda;
    const __half* We = W + (size_t)e * K * Wn + n0;
    const float*  be = bias + e * Wn + n0;

    const uint32_t smem_base = smem_u32(sm);

    auto load_chunk = [&](int c) {
        const int st = c % NSTG;
        const uint32_t abase = smem_base + st * STAGE_BYTES;
        const uint32_t bbase = abase + A_BYTES;
        const int k0 = c * BK;
#pragma unroll
        for (int i = 0; i < 4; i++) {            // A: 128 rows x 64B = 512 cp16
            int idx = tid + i * 128;
            int r = idx >> 2, ci = idx & 3;
            cp16(abase + (uint32_t)(r * A_RB + ci * 16),
                 Ae + (size_t)r * lda + k0 + ci * 8);
        }
#pragma unroll
        for (int i = 0; i < 4; i++) {            // B: 32 rows x 256B = 512 cp16
            int idx = tid + i * 128;
            int r = idx >> 4, ci = idx & 15;
            cp16(bbase + (uint32_t)(r * B_RB + ci * 16),
                 We + (size_t)(k0 + r) * Wn + ci * 8);
        }
    };

    float acc[4][8][4];
#pragma unroll
    for (int i = 0; i < 4; i++)
#pragma unroll
        for (int j = 0; j < 8; j++)
#pragma unroll
            for (int r = 0; r < 4; r++) acc[i][j][r] = 0.0f;

    const int nCh = K / BK;

    for (int c = 0; c < 3; c++) { load_chunk(c); cp_commit(); }

    const int a_row_l  = lane & 15;
    const int a_koff   = (lane >> 4) << 3;
    const int b_krow_l = lane & 15;
    const int b_noff   = (lane >> 4) << 3;

    for (int t = 0; t < nCh; t++) {
        cp_wait<2>();
        __syncthreads();
        // Load into stage (t+3)%4 == (t-1)%4: all warps finished reading it
        // (they passed the barrier above after computing iteration t-1).
        if (t + 3 < nCh) load_chunk(t + 3);
        cp_commit();

        const uint32_t abase = smem_base + (t % NSTG) * STAGE_BYTES;
        const uint32_t bbase = abase + A_BYTES;

#pragma unroll
        for (int kk = 0; kk < 2; kk++) {
            uint32_t af[4][4];
#pragma unroll
            for (int mt = 0; mt < 4; mt++) {
                uint32_t addr = abase + (uint32_t)((wm + mt * 16 + a_row_l) * A_RB
                                                   + (kk * 16 + a_koff) * 2);
                ldsm_x4(af[mt], addr);
            }
            uint32_t bf[8][2];
#pragma unroll
            for (int np = 0; np < 4; np++) {
                uint32_t r[4];
                uint32_t addr = bbase + (uint32_t)((kk * 16 + b_krow_l) * B_RB
                                                   + (wn + np * 16 + b_noff) * 2);
                ldsm_x4_trans(r, addr);
                bf[np * 2][0]     = r[0]; bf[np * 2][1]     = r[1];
                bf[np * 2 + 1][0] = r[2]; bf[np * 2 + 1][1] = r[3];
            }
#pragma unroll
            for (int mt = 0; mt < 4; mt++)
#pragma unroll
                for (int nt = 0; nt < 8; nt++)
                    mma16816(acc[mt][nt], af[mt], bf[nt]);
        }
    }

    // ---- epilogue ----
    if (outHalf) {
        __half* Ce = (__half*)C + (size_t)e * Wn;
#pragma unroll
        for (int mt = 0; mt < 4; mt++) {
#pragma unroll
            for (int nt = 0; nt < 8; nt++) {
                const int col = wn + nt * 8 + tig * 2;
                const float bx = be[col], by = be[col + 1];
                const int r0 = row0 + wm + mt * 16 + gid;
                float v0 = acc[mt][nt][0] + bx, v1 = acc[mt][nt][1] + by;
                float v2 = acc[mt][nt][2] + bx, v3 = acc[mt][nt][3] + by;
                if (relu) {
                    v0 = fmaxf(v0, 0.f); v1 = fmaxf(v1, 0.f);
                    v2 = fmaxf(v2, 0.f); v3 = fmaxf(v3, 0.f);
                }
                *(__half2*)(Ce + (size_t)r0 * (En * Wn) + n0 + col)       = __floats2half2_rn(v0, v1);
                *(__half2*)(Ce + (size_t)(r0 + 8) * (En * Wn) + n0 + col) = __floats2half2_rn(v2, v3);
            }
        }
    } else {
        float* Ce = (float*)C + (size_t)e * Wn;
#pragma unroll
        for (int mt = 0; mt < 4; mt++) {
#pragma unroll
            for (int nt = 0; nt < 8; nt++) {
                const int col = wn + nt * 8 + tig * 2;
                const float bx = be[col], by = be[col + 1];
                const int r0 = row0 + wm + mt * 16 + gid;
                float2 v0, v1;
                v0.x = acc[mt][nt][0] + bx; v0.y = acc[mt][nt][1] + by;
                v1.x = acc[mt][nt][2] + bx; v1.y = acc[mt][nt][3] + by;
                *(float2*)(Ce + (size_t)r0 * (En * Wn) + n0 + col)       = v0;
                *(float2*)(Ce + (size_t)(r0 + 8) * (En * Wn) + n0 + col) = v1;
            }
        }
    }
}

// ---------------------------------------------------------------------------
// Fused Gram-Schmidt + tanh-combine + per-task head
// ---------------------------------------------------------------------------
__device__ __forceinline__ float block_reduce_sum(float v, float* red) {
#pragma unroll
    for (int o = 16; o > 0; o >>= 1) v += __shfl_xor_sync(0xFFFFFFFFu, v, o);
    const int lane = threadIdx.x & 31, w = threadIdx.x >> 5;
    if (lane == 0) red[w] = v;
    __syncthreads();
    float s = (threadIdx.x < 8) ? red[threadIdx.x] : 0.0f;
    if (w == 0) {
#pragma unroll
        for (int o = 4; o > 0; o >>= 1) s += __shfl_xor_sync(0xFFu, s, o);
        if (lane == 0) red[0] = s;
    }
    __syncthreads();
    s = red[0];
    __syncthreads();
    return s;
}

__global__ __launch_bounds__(256)
void gs_head_kernel(const float* __restrict__ x, const float* __restrict__ eo,
                    const float* __restrict__ te_W, const float* __restrict__ head_W,
                    const float* __restrict__ head_b, float* __restrict__ out)
{
    __shared__ float sv[En][Wn];
    __shared__ float red[32];
    __shared__ float s_te[En];
    __shared__ int   s_idx;

    const int b = blockIdx.x;
    const int tid = threadIdx.x;

    {
        const float4* src = (const float4*)(eo + (size_t)b * (En * Wn));
        float4* dst = (float4*)&sv[0][0];
        for (int i = tid; i < En * Wn / 4; i += 256) dst[i] = src[i];
    }
    if (tid < En) {
        float s = 0.0f;
        for (int t = 0; t < Tn; t++)
            s += x[(size_t)b * XLD + OBS + t] * te_W[t * En + tid];
        s_te[tid] = s;
    }
    if (tid == 0) {
        float best = -1e30f; int bi = 0;
        for (int t = 0; t < Tn; t++) {
            float v = x[(size_t)b * XLD + OBS + t];
            if (v > best) { best = v; bi = t; }
        }
        s_idx = bi;
    }
    __syncthreads();

    {
        float p = 0.0f;
        for (int k = tid; k < Wn; k += 256) { float v = sv[0][k]; p += v * v; }
        float inv = 1.0f / (sqrtf(block_reduce_sum(p, red)) + EPSV);
        for (int k = tid; k < Wn; k += 256) sv[0][k] *= inv;
        __syncthreads();
    }
    for (int i = 1; i < En; i++) {
        float part[En - 1];
#pragma unroll
        for (int j = 0; j < En - 1; j++) part[j] = 0.0f;
        for (int k = tid; k < Wn; k += 256) {
            const float v = sv[i][k];
            for (int j = 0; j < i; j++) part[j] += v * sv[j][k];
        }
        float coeff[En - 1];
        for (int j = 0; j < i; j++) coeff[j] = block_reduce_sum(part[j], red);

        float nn = 0.0f;
        for (int k = tid; k < Wn; k += 256) {
            float w = sv[i][k];
            for (int j = 0; j < i; j++) w -= coeff[j] * sv[j][k];
            sv[i][k] = w;
            nn += w * w;
        }
        float inv = 1.0f / (sqrtf(block_reduce_sum(nn, red)) + EPSV);
        for (int k = tid; k < Wn; k += 256) sv[i][k] *= inv;
        __syncthreads();
    }

    const float* hw = head_W + (size_t)s_idx * Wn * Hn;
    float hacc[Hn];
#pragma unroll
    for (int h = 0; h < Hn; h++) hacc[h] = 0.0f;

    for (int k = tid; k < Wn; k += 256) {
        float f = 0.0f;
#pragma unroll
        for (int e = 0; e < En; e++) f += sv[e][k] * s_te[e];
        f = tanhf(f);
        const float* hwk = hw + (size_t)k * Hn;
#pragma unroll
        for (int h = 0; h < Hn; h++) hacc[h] += f * hwk[h];
    }
    for (int h = 0; h < Hn; h++) {
        float s = block_reduce_sum(hacc[h], red);
        if (tid == 0) out[(size_t)b * Hn + h] = s + head_b[s_idx * Hn + h];
    }
}

// ---------------------------------------------------------------------------
extern "C" void kernel_launch(void* const* d_in, const int* in_sizes, int n_in,
                              void* d_out, int out_size)
{
    const float* x      = (const float*)d_in[0];
    const float* te_W   = (const float*)d_in[1];
    const float* W0     = (const float*)d_in[2];
    const float* b0     = (const float*)d_in[3];
    const float* W1     = (const float*)d_in[4];
    const float* b1     = (const float*)d_in[5];
    const float* W2     = (const float*)d_in[6];
    const float* b2     = (const float*)d_in[7];
    const float* head_W = (const float*)d_in[8];
    const float* head_b = (const float*)d_in[9];
    float* out = (float*)d_out;

    __half *obsh, *wh, *h0, *h1;
    float *eo;
    cudaGetSymbolAddress((void**)&obsh, g_obsh);
    cudaGetSymbolAddress((void**)&wh,   g_wh);
    cudaGetSymbolAddress((void**)&h0,   g_h0);
    cudaGetSymbolAddress((void**)&h1,   g_h1);
    cudaGetSymbolAddress((void**)&eo,   g_eo);

    cudaFuncSetAttribute(gemm_fp16_kernel, cudaFuncAttributeMaxDynamicSharedMemorySize, GEMM_SMEM);

    cvt_half_kernel<<<2048, 256>>>(W0, wh + W0H_OFF, En * OBS * Wn);
    cvt_half_kernel<<<4096, 256>>>(W1, wh + W1H_OFF, En * Wn * Wn);
    cvt_half_kernel<<<4096, 256>>>(W2, wh + W2H_OFF, En * Wn * Wn);
    extract_obs_kernel<<<Bsz, 256>>>(x, obsh);

    dim3 grid(Wn / BN, Bsz / BM, En);   // (8, 32, 8)
    gemm_fp16_kernel<<<grid, 128, GEMM_SMEM>>>(obsh, wh + W0H_OFF, b0, h0, 512,  OBS,     0,  1, 1);
    gemm_fp16_kernel<<<grid, 128, GEMM_SMEM>>>(h0,   wh + W1H_OFF, b1, h1, 1024, En * Wn, Wn, 1, 1);
    gemm_fp16_kernel<<<grid, 128, GEMM_SMEM>>>(h1,   wh + W2H_OFF, b2, eo, 1024, En * Wn, Wn, 0, 0);

    gs_head_kernel<<<Bsz, 256>>>(x, eo, te_W, head_W, head_b, out);
}